// round 1
// baseline (speedup 1.0000x reference)
#include <cuda_runtime.h>
#include <stdint.h>

// Polar encoder, N=1024, K=512.
// One warp per batch row. Row is bit-packed: lane w holds codeword bits
// [32w, 32w+32). Butterfly stages 0..4 are in-word shift/mask XOR; stages
// 5..9 are cross-lane shfl_xor. Pack via ballot on coalesced loads,
// unpack via shfl + float4 stores.

#define PN 1024
#define PK 512
#define WARPS_PER_CTA 8

__device__ int g_fast;        // 1 iff info_pos[k] == (N-K)+k for all k
__device__ int g_inv[PN];     // codeword position -> info index k, or -1

__global__ void build_inv_kernel(const int* __restrict__ info_pos, int kcount) {
    int t = threadIdx.x;          // 1024 threads, 1 block
    if (t == 0) g_fast = 1;
    g_inv[t] = -1;
    __syncthreads();
    if (t < kcount) {
        int p = info_pos[t];
        g_inv[p] = t;
        if (p != (PN - kcount) + t) atomicAnd(&g_fast, 0);
    }
}

__global__ __launch_bounds__(32 * WARPS_PER_CTA)
void polar_encode_kernel(const float* __restrict__ u,
                         float* __restrict__ out,
                         int batch) {
    const int lane = threadIdx.x & 31;
    const int warp = threadIdx.x >> 5;
    const int row  = blockIdx.x * WARPS_PER_CTA + warp;
    if (row >= batch) return;

    __shared__ unsigned s_ubits[WARPS_PER_CTA][17];  // 16 info-bit words (+pad)

    const float* up = u + (size_t)row * PK;

    // ---- pack info bits: word j bit l = (u[row][32j+l] != 0) ----
#pragma unroll
    for (int j = 0; j < 16; j++) {
        float v = up[j * 32 + lane];
        unsigned b = __ballot_sync(0xffffffffu, v != 0.0f);
        if (lane == j) s_ubits[warp][j] = b;
    }
    __syncwarp();

    // ---- scatter info bits into codeword word owned by this lane ----
    unsigned x;
    if (g_fast) {
        // info_pos[k] == 512 + k: codeword word w = ubits[w-16] for w>=16
        x = (lane >= 16) ? s_ubits[warp][lane - 16] : 0u;
    } else {
        x = 0u;
        int base = lane << 5;
#pragma unroll 4
        for (int b = 0; b < 32; b++) {
            int k = g_inv[base + b];
            if (k >= 0)
                x |= ((s_ubits[warp][k >> 5] >> (k & 31)) & 1u) << b;
        }
    }

    // ---- butterfly stages 0..4 (within the 32-bit word) ----
    // x[p] ^= x[p + 2^s] for positions with bit s clear
    x ^= (x >> 1)  & 0x55555555u;
    x ^= (x >> 2)  & 0x33333333u;
    x ^= (x >> 4)  & 0x0f0f0f0fu;
    x ^= (x >> 8)  & 0x00ff00ffu;
    x ^= (x >> 16) & 0x0000ffffu;

    // ---- butterfly stages 5..9 (across lanes) ----
#pragma unroll
    for (int d = 1; d <= 16; d <<= 1) {
        unsigned y = __shfl_xor_sync(0xffffffffu, x, d);
        if ((lane & d) == 0) x ^= y;
    }

    // ---- unpack to float32, vectorized stores ----
    // lane l stores float4 at positions p = 128j + 4l .. +3
    // word index of p: 4j + (l>>3); bit index: 4*(l&7) + t
    float4* op = (float4*)(out + (size_t)row * PN);
    const int grp = lane >> 3;
    const int bb  = (lane & 7) * 4;
#pragma unroll
    for (int j = 0; j < 8; j++) {
        unsigned w = __shfl_sync(0xffffffffu, x, 4 * j + grp);
        float4 f;
        f.x = (float)((w >> (bb + 0)) & 1u);
        f.y = (float)((w >> (bb + 1)) & 1u);
        f.z = (float)((w >> (bb + 2)) & 1u);
        f.w = (float)((w >> (bb + 3)) & 1u);
        op[j * 32 + lane] = f;
    }
}

extern "C" void kernel_launch(void* const* d_in, const int* in_sizes, int n_in,
                              void* d_out, int out_size) {
    const float* u        = (const float*)d_in[0];
    const int*   info_pos = (const int*)d_in[1];
    // d_in[2] = ind_gather: butterfly structure is fixed by N; not needed.

    const int kcount = in_sizes[1];              // 512
    const int batch  = in_sizes[0] / kcount;     // 65536
    float* out = (float*)d_out;

    build_inv_kernel<<<1, PN>>>(info_pos, kcount);

    int ctas = (batch + WARPS_PER_CTA - 1) / WARPS_PER_CTA;
    polar_encode_kernel<<<ctas, 32 * WARPS_PER_CTA>>>(u, out, batch);
}

// round 2
// speedup vs baseline: 1.0240x; 1.0240x over previous
#include <cuda_runtime.h>
#include <stdint.h>

// Polar encoder, N=1024, K=512, fully fused single kernel.
// One warp per batch row, row bit-packed into 32 lanes x 32 bits.
// Stages 0..4: in-word shift/mask XOR. Stages 5..9: shfl_xor.
// info_pos scatter handled per-CTA: fast path (contiguous tail) is a lane
// remap; general path builds an inverse map in shared memory.

#define PN 1024
#define PK 512
#define WARPS_PER_CTA 8
#define CTA_THREADS (32 * WARPS_PER_CTA)

__global__ __launch_bounds__(CTA_THREADS)
void polar_encode_kernel(const float* __restrict__ u,
                         const int*   __restrict__ info_pos,
                         float* __restrict__ out,
                         int batch, int kcount) {
    const int tid  = threadIdx.x;
    const int lane = tid & 31;
    const int warp = tid >> 5;
    const int row  = blockIdx.x * WARPS_PER_CTA + warp;

    __shared__ int s_fast;
    __shared__ int s_inv[PN];                         // general path only
    __shared__ unsigned s_ubits[WARPS_PER_CTA][17];   // 16 info words (+pad)

    // ---- per-CTA: check fast layout (info_pos[k] == (N-K)+k, frozen%32==0) ----
    if (tid == 0) s_fast = ((PN - kcount) & 31) ? 0 : 1;
    __syncthreads();
    const int frozen = PN - kcount;
    for (int k = tid; k < kcount; k += CTA_THREADS) {
        if (info_pos[k] != frozen + k) s_fast = 0;    // benign race, all write 0
    }
    __syncthreads();
    const int fast = s_fast;

    if (!fast) {
        for (int i = tid; i < PN; i += CTA_THREADS) s_inv[i] = -1;
        __syncthreads();
        for (int k = tid; k < kcount; k += CTA_THREADS) s_inv[info_pos[k]] = k;
        __syncthreads();
    }

    if (row >= batch) return;

    const float* up = u + (size_t)row * PK;

    // ---- pack info bits: word j bit l = (u[row][32j+l] != 0) ----
#pragma unroll
    for (int j = 0; j < 16; j++) {
        float v = up[j * 32 + lane];
        unsigned b = __ballot_sync(0xffffffffu, v != 0.0f);
        if (lane == j) s_ubits[warp][j] = b;
    }
    __syncwarp();

    // ---- scatter info bits into this lane's codeword word ----
    unsigned x;
    if (fast) {
        const int fw = frozen >> 5;   // 16 for K=512
        x = (lane >= fw) ? s_ubits[warp][lane - fw] : 0u;
    } else {
        x = 0u;
        int base = lane << 5;
#pragma unroll 4
        for (int b = 0; b < 32; b++) {
            int k = s_inv[base + b];
            if (k >= 0)
                x |= ((s_ubits[warp][k >> 5] >> (k & 31)) & 1u) << b;
        }
    }

    // ---- butterfly stages 0..4 (within word) ----
    x ^= (x >> 1)  & 0x55555555u;
    x ^= (x >> 2)  & 0x33333333u;
    x ^= (x >> 4)  & 0x0f0f0f0fu;
    x ^= (x >> 8)  & 0x00ff00ffu;
    x ^= (x >> 16) & 0x0000ffffu;

    // ---- butterfly stages 5..9 (across lanes) ----
#pragma unroll
    for (int d = 1; d <= 16; d <<= 1) {
        unsigned y = __shfl_xor_sync(0xffffffffu, x, d);
        if ((lane & d) == 0) x ^= y;
    }

    // ---- unpack to float32 via bit trick (no I2F), float4 stores ----
    float4* op = (float4*)(out + (size_t)row * PN);
    const int grp = lane >> 3;
    const int bb  = (lane & 7) * 4;
#pragma unroll
    for (int j = 0; j < 8; j++) {
        unsigned w = __shfl_sync(0xffffffffu, x, 4 * j + grp);
        float4 f;
        f.x = __uint_as_float(((w >> (bb + 0)) & 1u) * 0x3f800000u);
        f.y = __uint_as_float(((w >> (bb + 1)) & 1u) * 0x3f800000u);
        f.z = __uint_as_float(((w >> (bb + 2)) & 1u) * 0x3f800000u);
        f.w = __uint_as_float(((w >> (bb + 3)) & 1u) * 0x3f800000u);
        op[j * 32 + lane] = f;
    }
}

extern "C" void kernel_launch(void* const* d_in, const int* in_sizes, int n_in,
                              void* d_out, int out_size) {
    const float* u        = (const float*)d_in[0];
    const int*   info_pos = (const int*)d_in[1];
    // d_in[2] = ind_gather: butterfly structure fixed by N; unused.

    const int kcount = in_sizes[1];              // 512
    const int batch  = in_sizes[0] / kcount;     // 65536
    float* out = (float*)d_out;

    int ctas = (batch + WARPS_PER_CTA - 1) / WARPS_PER_CTA;
    polar_encode_kernel<<<ctas, CTA_THREADS>>>(u, info_pos, out, batch, kcount);
}